// round 2
// baseline (speedup 1.0000x reference)
#include <cuda_runtime.h>
#include <cuda_bf16.h>

// DistortionLoss (eff_distloss) — single-kernel version for GB300.
//
// R1 -> R2 changes:
//  - Fused zero/main/finalize into ONE kernel using the threadfence-reduction
//    (last-block-done) pattern. The ticket counter is advanced with atomicInc
//    wrapping at gridDim.x-1, so it returns to 0 after every launch: no init
//    kernel required, deterministic, graph-capturable, allocation-free.
//  - Double-buffered row loads (prefetch next row's 3x float4 before computing
//    the current row) to keep HBM saturated across the warp-scan dep chain.
//  - __ldcs streaming loads (each byte read exactly once).
//  - Persistent grid: 1216 blocks (152 SMs x 8), warps grid-stride over rows.

#define LOSS_WEIGHT 0.01f
#define N_SAMPLES 128
#define GRID_BLOCKS 1216
#define BLOCK_THREADS 256

__device__ double   g_partials[GRID_BLOCKS];
__device__ unsigned g_ticket = 0;   // self-resetting via atomicInc wrap

__device__ __forceinline__ float row_contrib(
    float4 wv, float4 mv, float4 sv, int lane)
{
    // uni term partial: sum s*w^2 over this lane's 4 elements
    float uni = sv.x * wv.x * wv.x;
    uni = fmaf(sv.y * wv.y, wv.y, uni);
    uni = fmaf(sv.z * wv.z, wv.z, uni);
    uni = fmaf(sv.w * wv.w, wv.w, uni);

    // wm = w * m
    const float wm0 = wv.x * mv.x;
    const float wm1 = wv.y * mv.y;
    const float wm2 = wv.z * mv.z;
    const float wm3 = wv.w * mv.w;

    // local exclusive prefixes within the 4-element chunk
    const float eW1 = wv.x;
    const float eW2 = eW1 + wv.y;
    const float eW3 = eW2 + wv.z;
    const float tW  = eW3 + wv.w;     // lane total of w

    const float eM1 = wm0;
    const float eM2 = eM1 + wm1;
    const float eM3 = eM2 + wm2;
    const float tM  = eM3 + wm3;      // lane total of wm

    // warp inclusive scan of lane totals (w and wm together)
    float iW = tW, iM = tM;
    #pragma unroll
    for (int off = 1; off < 32; off <<= 1) {
        const float aW = __shfl_up_sync(0xffffffffu, iW, off);
        const float aM = __shfl_up_sync(0xffffffffu, iM, off);
        if (lane >= off) { iW += aW; iM += aM; }
    }
    const float EW = iW - tW;   // exclusive warp prefix of w
    const float EM = iM - tM;   // exclusive warp prefix of wm

    // bi term: sum_k wm_k * exW_k - w_k * exWM_k  (exclusive prefixes)
    float bi;
    bi  = wm0 * EW          - wv.x * EM;
    bi += wm1 * (EW + eW1)  - wv.y * (EM + eM1);
    bi += wm2 * (EW + eW2)  - wv.z * (EM + eM2);
    bi += wm3 * (EW + eW3)  - wv.w * (EM + eM3);

    return (1.0f / 3.0f) * uni + 2.0f * bi;
}

__global__ __launch_bounds__(BLOCK_THREADS) void dl_fused_kernel(
    const float* __restrict__ w,
    const float* __restrict__ m,
    const float* __restrict__ s,
    float* __restrict__ out,
    int B, float scale)
{
    const int lane   = threadIdx.x & 31;
    const int warpIn = threadIdx.x >> 5;
    const int gwarp  = (blockIdx.x * BLOCK_THREADS + threadIdx.x) >> 5;
    const int nwarps = (gridDim.x * BLOCK_THREADS) >> 5;

    float acc = 0.0f;

    int row = gwarp;
    if (row < B) {
        size_t base = (size_t)row * N_SAMPLES;
        float4 wv = __ldcs(reinterpret_cast<const float4*>(w + base) + lane);
        float4 mv = __ldcs(reinterpret_cast<const float4*>(m + base) + lane);
        float4 sv = __ldcs(reinterpret_cast<const float4*>(s + base) + lane);

        while (true) {
            const int next = row + nwarps;
            float4 wn, mn, sn;
            if (next < B) {
                const size_t nb = (size_t)next * N_SAMPLES;
                wn = __ldcs(reinterpret_cast<const float4*>(w + nb) + lane);
                mn = __ldcs(reinterpret_cast<const float4*>(m + nb) + lane);
                sn = __ldcs(reinterpret_cast<const float4*>(s + nb) + lane);
            }
            acc += row_contrib(wv, mv, sv, lane);
            if (next >= B) break;
            wv = wn; mv = mn; sv = sn;
            row = next;
        }
    }

    // warp reduce
    #pragma unroll
    for (int off = 16; off > 0; off >>= 1)
        acc += __shfl_down_sync(0xffffffffu, acc, off);

    __shared__ float warp_sums[BLOCK_THREADS / 32];
    if (lane == 0) warp_sums[warpIn] = acc;
    __syncthreads();

    __shared__ bool is_last;
    if (threadIdx.x == 0) {
        float blockAcc = 0.0f;
        #pragma unroll
        for (int i = 0; i < BLOCK_THREADS / 32; i++) blockAcc += warp_sums[i];
        g_partials[blockIdx.x] = (double)blockAcc;
        __threadfence();
        // atomicInc wraps to 0 after gridDim.x increments -> counter is 0
        // again at the end of every launch (no init kernel needed).
        const unsigned ticket = atomicInc(&g_ticket, gridDim.x - 1);
        is_last = (ticket == gridDim.x - 1);
    }
    __syncthreads();

    if (is_last) {
        __threadfence();
        double t = 0.0;
        for (int i = threadIdx.x; i < (int)gridDim.x; i += BLOCK_THREADS)
            t += g_partials[i];
        // warp reduce (double)
        #pragma unroll
        for (int off = 16; off > 0; off >>= 1)
            t += __shfl_down_sync(0xffffffffu, t, off);
        __shared__ double dsums[BLOCK_THREADS / 32];
        if (lane == 0) dsums[warpIn] = t;
        __syncthreads();
        if (threadIdx.x == 0) {
            double total = 0.0;
            #pragma unroll
            for (int i = 0; i < BLOCK_THREADS / 32; i++) total += dsums[i];
            out[0] = (float)(total * (double)scale);
        }
    }
}

extern "C" void kernel_launch(void* const* d_in, const int* in_sizes, int n_in,
                              void* d_out, int out_size) {
    const float* w = (const float*)d_in[0];
    const float* m = (const float*)d_in[1];
    const float* s = (const float*)d_in[2];
    float* out = (float*)d_out;

    const int B = in_sizes[0] / N_SAMPLES;

    int blocks = GRID_BLOCKS;
    const int totalWarps = blocks * (BLOCK_THREADS / 32);
    if (totalWarps > B) {
        blocks = (B + (BLOCK_THREADS / 32) - 1) / (BLOCK_THREADS / 32);
        if (blocks < 1) blocks = 1;
    }
    dl_fused_kernel<<<blocks, BLOCK_THREADS>>>(w, m, s, out, B,
                                               LOSS_WEIGHT / (float)B);
}